// round 9
// baseline (speedup 1.0000x reference)
#include <cuda_runtime.h>
#include <cuda_fp16.h>
#include <cstdint>

// out[i,j,o] = sum_h x[i+1,h]*x[j+1,h]*W[o,h] + b[o]
// (diff/W2 term is antisymmetric -> cancels under (P+P^T)/2 symmetrization)
//
// D_o = A_o B^T, A_o = X .* w_o, B = X (512x768 f32)
// fp32 approximated by ASYMMETRIC fp16 split: a*b ~= fp16(a)*(bhi+blo),
// 2 MMAs per k16 per channel (error ~2^-12 rel, well under 1e-3).
// Single fused kernel: LDG fp32 -> scale/split -> STS, no prep pass.
// Upper-tri 32x32 tiles (mirror), split-K=2 inside the CTA (2 groups x
// 4 warps, group-scoped barriers), plain coalesced STG epilogue.

#define HDIM 768
#define KC 32                     // k per chunk
#define NKCG 12                   // chunks per group (768 / 32 / 2)
#define ROW_B 80                  // 64 B data + 16 B pad (conflict-free LDSM)
#define TILE_B (32 * ROW_B)       // 2560 B (32 rows x 32 fp16)
#define NTILE 4                   // A0h A1h Bh Bl
#define STAGE_B (NTILE * TILE_B)  // 10240 B
#define GRP_B (2 * STAGE_B)       // 20480 B (2 stages)
#define SMEM_TOTAL (2 * GRP_B)    // 40960 B (< 48K, no attr needed)
#define FIN_STRIDE 66             // final tile row stride in floats

__device__ __forceinline__ uint32_t smem_u32(const void* p) {
    uint32_t a;
    asm("{ .reg .u64 t; cvta.to.shared.u64 t, %1; cvt.u32.u64 %0, t; }"
        : "=r"(a) : "l"(p));
    return a;
}

__device__ __forceinline__ void sts128(uint32_t dst, uint32_t r0, uint32_t r1,
                                       uint32_t r2, uint32_t r3) {
    asm volatile("st.shared.v4.b32 [%0], {%1,%2,%3,%4};"
                 :: "r"(dst), "r"(r0), "r"(r1), "r"(r2), "r"(r3) : "memory");
}

__device__ __forceinline__ void ldsm4(uint32_t* r, uint32_t addr) {
    asm volatile("ldmatrix.sync.aligned.m8n8.x4.shared.b16 {%0,%1,%2,%3}, [%4];"
                 : "=r"(r[0]), "=r"(r[1]), "=r"(r[2]), "=r"(r[3]) : "r"(addr));
}

__device__ __forceinline__ void mmaf16(float* c, const uint32_t* a,
                                       uint32_t b0, uint32_t b1) {
    asm volatile(
        "mma.sync.aligned.m16n8k16.row.col.f32.f16.f16.f32 "
        "{%0,%1,%2,%3}, {%4,%5,%6,%7}, {%8,%9}, {%0,%1,%2,%3};"
        : "+f"(c[0]), "+f"(c[1]), "+f"(c[2]), "+f"(c[3])
        : "r"(a[0]), "r"(a[1]), "r"(a[2]), "r"(a[3]), "r"(b0), "r"(b1));
}

__device__ __forceinline__ void grp_bar(int id) {
    asm volatile("bar.sync %0, 128;" :: "r"(id) : "memory");
}

__device__ __forceinline__ uint32_t pk(float a, float b) {
    __half2 h = __floats2half2_rn(a, b);
    return *(uint32_t*)&h;
}

__global__ void __launch_bounds__(256, 1)
pairwise_kernel(const float* __restrict__ x, const float* __restrict__ W,
                const float* __restrict__ bias, float* __restrict__ out)
{
    // Triangular decode: blockIdx.x in [0,136) -> (bi, bj), bj >= bi
    int t = blockIdx.x;
    int bi = 0;
    while (t >= 16 - bi) { t -= 16 - bi; bi++; }
    const int bj = bi + t;

    extern __shared__ __align__(16) char smem[];
    const uint32_t sbase = smem_u32(smem);

    const int tid  = threadIdx.x;
    const int grp  = tid >> 7;        // K-group 0/1
    const int gtid = tid & 127;
    const int wid  = gtid >> 5;
    const int lane = tid & 31;
    const int wm = wid >> 1;          // warp row (0..1) of 16
    const int wn = wid & 1;           // warp col (0..1) of 16

    const uint32_t gb = sbase + grp * GRP_B;
    const int lrow  = gtid >> 2;      // 0..31 tile row
    const int lc    = gtid & 3;       // 8-col group within 32
    const int kbase = grp * (HDIM / 2);

    const float* xi  = x + (size_t)(bi * 32 + lrow) * HDIM + kbase + lc * 8;
    const float* xj  = x + (size_t)(bj * 32 + lrow) * HDIM + kbase + lc * 8;
    const float* w0p = W + kbase + lc * 8;
    const float* w1p = W + 1536 + kbase + lc * 8;

    float xa[8], xb[8], w0[8], w1[8];   // prefetch registers

    auto ldg_chunk = [&](int kc) {
        const int o = kc * KC;
        *(float4*)(xa)     = *(const float4*)(xi + o);
        *(float4*)(xa + 4) = *(const float4*)(xi + o + 4);
        *(float4*)(xb)     = *(const float4*)(xj + o);
        *(float4*)(xb + 4) = *(const float4*)(xj + o + 4);
        *(float4*)(w0)     = *(const float4*)(w0p + o);
        *(float4*)(w0 + 4) = *(const float4*)(w0p + o + 4);
        *(float4*)(w1)     = *(const float4*)(w1p + o);
        *(float4*)(w1 + 4) = *(const float4*)(w1p + o + 4);
    };

    auto sts_chunk = [&](int sl) {
        const uint32_t dst = gb + sl * STAGE_B + lrow * ROW_B + lc * 16;
        // A0h = fp16(x_i * w0), A1h = fp16(x_i * w1)
        sts128(dst + 0 * TILE_B,
               pk(xa[0] * w0[0], xa[1] * w0[1]), pk(xa[2] * w0[2], xa[3] * w0[3]),
               pk(xa[4] * w0[4], xa[5] * w0[5]), pk(xa[6] * w0[6], xa[7] * w0[7]));
        sts128(dst + 1 * TILE_B,
               pk(xa[0] * w1[0], xa[1] * w1[1]), pk(xa[2] * w1[2], xa[3] * w1[3]),
               pk(xa[4] * w1[4], xa[5] * w1[5]), pk(xa[6] * w1[6], xa[7] * w1[7]));
        // Bh = fp16(x_j), Bl = fp16(x_j - Bh)
        __half hb[8];
        float  lb[8];
#pragma unroll
        for (int u = 0; u < 8; u++) {
            hb[u] = __float2half_rn(xb[u]);
            lb[u] = xb[u] - __half2float(hb[u]);
        }
        uint32_t bh0, bh1, bh2, bh3;
        { __half2 h;
          h = __halves2half2(hb[0], hb[1]); bh0 = *(uint32_t*)&h;
          h = __halves2half2(hb[2], hb[3]); bh1 = *(uint32_t*)&h;
          h = __halves2half2(hb[4], hb[5]); bh2 = *(uint32_t*)&h;
          h = __halves2half2(hb[6], hb[7]); bh3 = *(uint32_t*)&h; }
        sts128(dst + 2 * TILE_B, bh0, bh1, bh2, bh3);
        sts128(dst + 3 * TILE_B,
               pk(lb[0], lb[1]), pk(lb[2], lb[3]),
               pk(lb[4], lb[5]), pk(lb[6], lb[7]));
    };

    // acc[ch][term][nf][4], term: 0 = A*Bhi, 1 = A*Blo
    float acc0[2][2][4] = {};
    float acc1[2][2][4] = {};

    const uint32_t arow = (uint32_t)(wm * 16 + (lane & 15)) * ROW_B
                        + ((lane >> 4) << 4);
    const uint32_t brow = (uint32_t)(wn * 16 + (lane & 15)) * ROW_B
                        + ((lane >> 4) << 4);

    auto compute = [&](int sl) {
        const uint32_t tb = gb + sl * STAGE_B;
#pragma unroll
        for (int h = 0; h < 2; h++) {           // two k16 slices of k32
            uint32_t a0[4], a1[4], bh[4], bl[4];
            ldsm4(a0, tb + 0 * TILE_B + arow + h * 32);
            ldsm4(a1, tb + 1 * TILE_B + arow + h * 32);
            ldsm4(bh, tb + 2 * TILE_B + brow + h * 32);
            ldsm4(bl, tb + 3 * TILE_B + brow + h * 32);
#pragma unroll
            for (int nf = 0; nf < 2; nf++) {
                mmaf16(acc0[0][nf], a0, bh[nf], bh[nf + 2]);
                mmaf16(acc1[0][nf], a1, bh[nf], bh[nf + 2]);
                mmaf16(acc0[1][nf], a0, bl[nf], bl[nf + 2]);
                mmaf16(acc1[1][nf], a1, bl[nf], bl[nf + 2]);
            }
        }
    };

    // ---- fused pipeline: LDG(+1 chunk ahead) -> cvt/STS -> MMA ----
    const int barid = grp + 1;
    ldg_chunk(0);
    sts_chunk(0);
    ldg_chunk(1);
    grp_bar(barid);

#pragma unroll 1
    for (int kc = 0; kc < NKCG; kc++) {
        if (kc + 1 < NKCG) sts_chunk((kc + 1) & 1);   // regs of kc+1 -> smem
        if (kc + 2 < NKCG) ldg_chunk(kc + 2);          // refill regs
        compute(kc & 1);
        grp_bar(barid);
    }

    // ---- combine K-halves via smem, then coalesced STG ----
    __syncthreads();
    float* part = (float*)(smem + GRP_B);
    float* fin  = (float*)smem;

    if (grp == 1) {
#pragma unroll
        for (int nf = 0; nf < 2; nf++)
#pragma unroll
            for (int r = 0; r < 4; r++) {
                const int idx = ((gtid * 2 + nf) * 4 + r) * 2;
                part[idx + 0] = acc0[0][nf][r] + acc0[1][nf][r];
                part[idx + 1] = acc1[0][nf][r] + acc1[1][nf][r];
            }
    }
    __syncthreads();

    if (grp == 0) {
        const float bv0 = bias[0];
        const float bv1 = bias[1];
#pragma unroll
        for (int nf = 0; nf < 2; nf++)
#pragma unroll
            for (int r = 0; r < 4; r++) {
                const int idx = ((gtid * 2 + nf) * 4 + r) * 2;
                const float v0 = acc0[0][nf][r] + acc0[1][nf][r]
                               + part[idx + 0] + bv0;
                const float v1 = acc1[0][nf][r] + acc1[1][nf][r]
                               + part[idx + 1] + bv1;
                const int ii = wm * 16 + (lane >> 2) + ((r >> 1) << 3);
                const int jj = wn * 16 + nf * 8 + ((lane & 3) << 1) + (r & 1);
                fin[ii * FIN_STRIDE + jj * 2 + 0] = v0;
                fin[ii * FIN_STRIDE + jj * 2 + 1] = v1;
            }
    }
    __syncthreads();

    const int ib = bi * 32;
    const int jb = bj * 32;

    // Direct pass: row ii -> out[(gi-1)][jb..jb+31][:], contiguous float2
    {
        const int ii = tid >> 3;
        const int q4 = (tid & 7) * 4;
        const int gi = ib + ii;
        if (gi >= 1 && gi <= 510) {
            float* orow = out + (size_t)(gi - 1) * 1020;
#pragma unroll
            for (int u = 0; u < 4; u++) {
                const int jj = q4 + u;
                const int gj = jb + jj;
                if (gj >= 1 && gj <= 510) {
                    float2 v = *(float2*)(fin + ii * FIN_STRIDE + jj * 2);
                    *(float2*)(orow + (size_t)(gj - 1) * 2) = v;
                }
            }
        }
    }
    // Mirror pass (off-diagonal tiles)
    if (bi != bj) {
        const int jj = tid >> 3;
        const int q4 = (tid & 7) * 4;
        const int gj = jb + jj;
        if (gj >= 1 && gj <= 510) {
            float* orow = out + (size_t)(gj - 1) * 1020;
#pragma unroll
            for (int u = 0; u < 4; u++) {
                const int ii = q4 + u;
                const int gi = ib + ii;
                if (gi >= 1 && gi <= 510) {
                    float2 v = *(float2*)(fin + ii * FIN_STRIDE + jj * 2);
                    *(float2*)(orow + (size_t)(gi - 1) * 2) = v;
                }
            }
        }
    }
}

// ---------------------------------------------------------------------------
extern "C" void kernel_launch(void* const* d_in, const int* in_sizes, int n_in,
                              void* d_out, int out_size)
{
    const float* x = (const float*)d_in[0];   // (1, 512, 768)
    const float* W = (const float*)d_in[1];   // (2, 1536)
    const float* b = (const float*)d_in[2];   // (2,)
    float* out = (float*)d_out;               // (510, 510, 2)

    pairwise_kernel<<<136, 256, SMEM_TOTAL>>>(x, W, b, out);
}

// round 10
// speedup vs baseline: 1.2987x; 1.2987x over previous
#include <cuda_runtime.h>
#include <cuda_fp16.h>
#include <cstdint>

// out[i,j,o] = sum_h x[i+1,h]*x[j+1,h]*W[o,h] + b[o]
// (diff/W2 term is antisymmetric -> cancels under (P+P^T)/2 symmetrization)
//
// D_o = A_o B^T, A_o = X .* w_o, B = X (512x768 f32)
// fp32 approximated by ASYMMETRIC fp16 split: a*b ~= fp16(a)*(bhi+blo)
// (2 MMAs per k16 per channel; measured rel_err ~2e-4 < 1e-3).
// Prep kernel pre-converts 4 fp16 images; main kernel is a pure
// cp.async -> ldmatrix -> HMMA pipeline (no convert math in MMA warps).
// Upper-tri 32x32 tiles (mirror), split-K=2 inside CTA (2 groups x 4 warps,
// group-scoped barriers), smem-staged coalesced STG. No atomics.

#define HDIM 768
#define KC 64                     // k per chunk (64 fp16 = 128 B rows)
#define NKCG 6                    // chunks per group (768 / 64 / 2)
#define ROW_B 144                 // 128 B data + 16 B pad (conflict-free LDSM)
#define TILE_B (32 * ROW_B)       // 4608 B (32 rows x 64 fp16)
#define NTILE 4                   // A0h A1h Bh Bl
#define STAGE_B (NTILE * TILE_B)  // 18432 B
#define GRP_B (2 * STAGE_B)       // 36864 B (2 stages)
#define SMEM_TOTAL (2 * GRP_B)    // 73728 B (1 CTA/SM)
#define FIN_STRIDE 66             // final tile row stride in floats

// fp16 images: 0:A0h 1:A1h 2:Bh 3:Bl  (row-major [512][768])
__device__ __half g_img[4][512 * HDIM];

// ---------------------------------------------------------------------------
union PackH8 { __half h[8]; uint4 v; };

__global__ void prep_kernel(const float* __restrict__ x,
                            const float* __restrict__ W)
{
    int gid = blockIdx.x * blockDim.x + threadIdx.x;
    if (gid >= 512 * (HDIM / 8)) return;
    int i  = gid / (HDIM / 8);
    int k0 = (gid % (HDIM / 8)) * 8;

    float4 x0 = *(const float4*)(x + (size_t)i * HDIM + k0);
    float4 x1 = *(const float4*)(x + (size_t)i * HDIM + k0 + 4);
    float4 wa0 = *(const float4*)(W + k0);
    float4 wa1 = *(const float4*)(W + k0 + 4);
    float4 wb0 = *(const float4*)(W + 1536 + k0);
    float4 wb1 = *(const float4*)(W + 1536 + k0 + 4);

    float xs[8] = {x0.x, x0.y, x0.z, x0.w, x1.x, x1.y, x1.z, x1.w};
    float w0[8] = {wa0.x, wa0.y, wa0.z, wa0.w, wa1.x, wa1.y, wa1.z, wa1.w};
    float w1[8] = {wb0.x, wb0.y, wb0.z, wb0.w, wb1.x, wb1.y, wb1.z, wb1.w};

    PackH8 a0, a1, bh, bl;
#pragma unroll
    for (int t = 0; t < 8; t++) {
        a0.h[t] = __float2half_rn(xs[t] * w0[t]);
        a1.h[t] = __float2half_rn(xs[t] * w1[t]);
        __half h = __float2half_rn(xs[t]);
        bh.h[t] = h;
        bl.h[t] = __float2half_rn(xs[t] - __half2float(h));
    }
    size_t off = (size_t)i * HDIM + k0;
    *(uint4*)(&g_img[0][off]) = a0.v;
    *(uint4*)(&g_img[1][off]) = a1.v;
    *(uint4*)(&g_img[2][off]) = bh.v;
    *(uint4*)(&g_img[3][off]) = bl.v;
}

// ---------------------------------------------------------------------------
__device__ __forceinline__ uint32_t smem_u32(const void* p) {
    uint32_t a;
    asm("{ .reg .u64 t; cvta.to.shared.u64 t, %1; cvt.u32.u64 %0, t; }"
        : "=r"(a) : "l"(p));
    return a;
}

__device__ __forceinline__ void cp16(uint32_t dst, const void* src) {
    asm volatile("cp.async.cg.shared.global [%0], [%1], 16;"
                 :: "r"(dst), "l"(src) : "memory");
}

__device__ __forceinline__ void ldsm4(uint32_t* r, uint32_t addr) {
    asm volatile("ldmatrix.sync.aligned.m8n8.x4.shared.b16 {%0,%1,%2,%3}, [%4];"
                 : "=r"(r[0]), "=r"(r[1]), "=r"(r[2]), "=r"(r[3]) : "r"(addr));
}

__device__ __forceinline__ void mmaf16(float* c, const uint32_t* a,
                                       uint32_t b0, uint32_t b1) {
    asm volatile(
        "mma.sync.aligned.m16n8k16.row.col.f32.f16.f16.f32 "
        "{%0,%1,%2,%3}, {%4,%5,%6,%7}, {%8,%9}, {%0,%1,%2,%3};"
        : "+f"(c[0]), "+f"(c[1]), "+f"(c[2]), "+f"(c[3])
        : "r"(a[0]), "r"(a[1]), "r"(a[2]), "r"(a[3]), "r"(b0), "r"(b1));
}

__device__ __forceinline__ void grp_bar(int id) {
    asm volatile("bar.sync %0, 128;" :: "r"(id) : "memory");
}

__global__ void __launch_bounds__(256, 1)
pairwise_mma_kernel(const float* __restrict__ bias, float* __restrict__ out)
{
    // Triangular decode: blockIdx.x in [0,136) -> (bi, bj), bj >= bi
    int t = blockIdx.x;
    int bi = 0;
    while (t >= 16 - bi) { t -= 16 - bi; bi++; }
    const int bj = bi + t;

    extern __shared__ __align__(16) char smem[];
    const uint32_t sbase = smem_u32(smem);

    const int tid  = threadIdx.x;
    const int grp  = tid >> 7;        // K-group 0/1
    const int gtid = tid & 127;
    const int wid  = gtid >> 5;
    const int lane = tid & 31;
    const int wm = wid >> 1;          // warp row (0..1) of 16
    const int wn = wid & 1;           // warp col (0..1) of 16

    const __half* src[NTILE];
    src[0] = &g_img[0][(size_t)(bi * 32) * HDIM];
    src[1] = &g_img[1][(size_t)(bi * 32) * HDIM];
    src[2] = &g_img[2][(size_t)(bj * 32) * HDIM];
    src[3] = &g_img[3][(size_t)(bj * 32) * HDIM];

    const uint32_t gb = sbase + grp * GRP_B;
    const int lrow = gtid >> 2;       // 0..31 tile row
    const int lc   = gtid & 3;        // 16B chunk index (of 4 per half-row)
    const int kofs = grp * NKCG;      // this group's first chunk

    auto issue = [&](int kc, int sl) {
        const uint32_t dbase = gb + sl * STAGE_B + lrow * ROW_B + lc * 16;
        const int kcol = (kofs + kc) * KC + lc * 8;
#pragma unroll
        for (int q = 0; q < NTILE; q++) {
            const __half* s = src[q] + (size_t)lrow * HDIM + kcol;
            cp16(dbase + q * TILE_B,      s);
            cp16(dbase + q * TILE_B + 64, s + 32);
        }
    };

    // acc[ch][term][nf][4], term: 0 = A*Bhi, 1 = A*Blo
    float acc0[2][2][4] = {};
    float acc1[2][2][4] = {};

    const uint32_t arow = (uint32_t)(wm * 16 + (lane & 15)) * ROW_B
                        + ((lane >> 4) << 4);
    const uint32_t brow = (uint32_t)(wn * 16 + (lane & 15)) * ROW_B
                        + ((lane >> 4) << 4);

    auto compute = [&](int sl) {
        const uint32_t tb = gb + sl * STAGE_B;
#pragma unroll
        for (int h = 0; h < 4; h++) {           // four k16 slices of k64
            uint32_t a0[4], a1[4], bh[4], bl[4];
            ldsm4(a0, tb + 0 * TILE_B + arow + h * 32);
            ldsm4(a1, tb + 1 * TILE_B + arow + h * 32);
            ldsm4(bh, tb + 2 * TILE_B + brow + h * 32);
            ldsm4(bl, tb + 3 * TILE_B + brow + h * 32);
#pragma unroll
            for (int nf = 0; nf < 2; nf++) {
                mmaf16(acc0[0][nf], a0, bh[nf], bh[nf + 2]);
                mmaf16(acc1[0][nf], a1, bh[nf], bh[nf + 2]);
                mmaf16(acc0[1][nf], a0, bl[nf], bl[nf + 2]);
                mmaf16(acc1[1][nf], a1, bl[nf], bl[nf + 2]);
            }
        }
    };

    // ---- per-group 2-stage cp.async pipeline over 6 chunks ----
    const int barid = grp + 1;
    issue(0, 0);
    asm volatile("cp.async.commit_group;" ::: "memory");
    issue(1, 1);
    asm volatile("cp.async.commit_group;" ::: "memory");

#pragma unroll 1
    for (int kc = 0; kc < NKCG; kc++) {
        if (kc < NKCG - 1)
            asm volatile("cp.async.wait_group 1;" ::: "memory");
        else
            asm volatile("cp.async.wait_group 0;" ::: "memory");
        grp_bar(barid);
        compute(kc & 1);
        grp_bar(barid);
        if (kc + 2 < NKCG) {
            issue(kc + 2, kc & 1);
            asm volatile("cp.async.commit_group;" ::: "memory");
        }
    }

    // ---- combine K-halves via smem, then coalesced STG ----
    __syncthreads();
    float* part = (float*)(smem + GRP_B);
    float* fin  = (float*)smem;

    if (grp == 1) {
#pragma unroll
        for (int nf = 0; nf < 2; nf++)
#pragma unroll
            for (int r = 0; r < 4; r++) {
                const int idx = ((gtid * 2 + nf) * 4 + r) * 2;
                part[idx + 0] = acc0[0][nf][r] + acc0[1][nf][r];
                part[idx + 1] = acc1[0][nf][r] + acc1[1][nf][r];
            }
    }
    __syncthreads();

    if (grp == 0) {
        const float bv0 = bias[0];
        const float bv1 = bias[1];
#pragma unroll
        for (int nf = 0; nf < 2; nf++)
#pragma unroll
            for (int r = 0; r < 4; r++) {
                const int idx = ((gtid * 2 + nf) * 4 + r) * 2;
                const float v0 = acc0[0][nf][r] + acc0[1][nf][r]
                               + part[idx + 0] + bv0;
                const float v1 = acc1[0][nf][r] + acc1[1][nf][r]
                               + part[idx + 1] + bv1;
                const int ii = wm * 16 + (lane >> 2) + ((r >> 1) << 3);
                const int jj = wn * 16 + nf * 8 + ((lane & 3) << 1) + (r & 1);
                fin[ii * FIN_STRIDE + jj * 2 + 0] = v0;
                fin[ii * FIN_STRIDE + jj * 2 + 1] = v1;
            }
    }
    __syncthreads();

    const int ib = bi * 32;
    const int jb = bj * 32;

    // Direct pass: row ii -> out[(gi-1)][jb..jb+31][:], contiguous float2
    {
        const int ii = tid >> 3;
        const int q4 = (tid & 7) * 4;
        const int gi = ib + ii;
        if (gi >= 1 && gi <= 510) {
            float* orow = out + (size_t)(gi - 1) * 1020;
#pragma unroll
            for (int u = 0; u < 4; u++) {
                const int jj = q4 + u;
                const int gj = jb + jj;
                if (gj >= 1 && gj <= 510) {
                    float2 v = *(float2*)(fin + ii * FIN_STRIDE + jj * 2);
                    *(float2*)(orow + (size_t)(gj - 1) * 2) = v;
                }
            }
        }
    }
    // Mirror pass (off-diagonal tiles)
    if (bi != bj) {
        const int jj = tid >> 3;
        const int q4 = (tid & 7) * 4;
        const int gj = jb + jj;
        if (gj >= 1 && gj <= 510) {
            float* orow = out + (size_t)(gj - 1) * 1020;
#pragma unroll
            for (int u = 0; u < 4; u++) {
                const int ii = q4 + u;
                const int gi = ib + ii;
                if (gi >= 1 && gi <= 510) {
                    float2 v = *(float2*)(fin + ii * FIN_STRIDE + jj * 2);
                    *(float2*)(orow + (size_t)(gi - 1) * 2) = v;
                }
            }
        }
    }
}

// ---------------------------------------------------------------------------
extern "C" void kernel_launch(void* const* d_in, const int* in_sizes, int n_in,
                              void* d_out, int out_size)
{
    const float* x = (const float*)d_in[0];   // (1, 512, 768)
    const float* W = (const float*)d_in[1];   // (2, 1536)
    const float* b = (const float*)d_in[2];   // (2,)
    float* out = (float*)d_out;               // (510, 510, 2)

    cudaFuncSetAttribute(pairwise_mma_kernel,
                         cudaFuncAttributeMaxDynamicSharedMemorySize, SMEM_TOTAL);

    prep_kernel<<<192, 256>>>(x, W);
    pairwise_mma_kernel<<<136, 256, SMEM_TOTAL>>>(b, out);
}

// round 11
// speedup vs baseline: 1.3333x; 1.0267x over previous
#include <cuda_runtime.h>
#include <cuda_fp16.h>
#include <cstdint>

// out[i,j,o] = sum_h x[i+1,h]*x[j+1,h]*W[o,h] + b[o]
// (diff/W2 term is antisymmetric -> cancels under (P+P^T)/2 symmetrization)
//
// D_o = A_o B^T, A_o = X .* w_o, B = X (512x768 f32)
// fp32 approximated by ASYMMETRIC fp16 split: a*b ~= fp16(a)*(bhi+blo)
// (2 MMAs per k16 per channel; measured rel_err ~2e-4 < 1e-3).
// Prep kernel pre-converts 4 fp16 images. Main kernel: 512 threads,
// 4 K-groups x 4 warps (split-K=4 in-CTA), 4-stage cp.async pipeline with
// ONE group barrier per chunk, pure ldmatrix+HMMA inner loop, smem combine,
// coalesced STG. Upper-tri 32x32 tiles + mirror. No atomics.

#define HDIM 768
#define NGRP 4
#define KC 32                     // k per chunk (32 fp16 = 64 B rows)
#define NKCG 6                    // chunks per group (768 / 32 / 4)
#define ROW_B 80                  // 64 B data + 16 B pad (conflict-free LDSM)
#define TILE_B (32 * ROW_B)       // 2560 B (32 rows x 32 fp16)
#define NTILE 4                   // A0h A1h Bh Bl
#define STAGE_B (NTILE * TILE_B)  // 10240 B
#define NSTAGE 4
#define GRP_B (NSTAGE * STAGE_B)  // 40960 B
#define SMEM_TOTAL (NGRP * GRP_B) // 163840 B (1 CTA/SM)
#define FIN_STRIDE 66             // final tile row stride in floats
#define FIN_B 8448                // 32 * 66 * 4
#define PART_FLOATS 2048          // 32x32x2 floats per partial buffer

// fp16 images: 0:A0h 1:A1h 2:Bh 3:Bl  (row-major [512][768])
__device__ __half g_img[4][512 * HDIM];

// ---------------------------------------------------------------------------
union PackH8 { __half h[8]; uint4 v; };

__global__ void prep_kernel(const float* __restrict__ x,
                            const float* __restrict__ W)
{
    int gid = blockIdx.x * blockDim.x + threadIdx.x;
    if (gid >= 512 * (HDIM / 8)) return;
    int i  = gid / (HDIM / 8);
    int k0 = (gid % (HDIM / 8)) * 8;

    float4 x0 = *(const float4*)(x + (size_t)i * HDIM + k0);
    float4 x1 = *(const float4*)(x + (size_t)i * HDIM + k0 + 4);
    float4 wa0 = *(const float4*)(W + k0);
    float4 wa1 = *(const float4*)(W + k0 + 4);
    float4 wb0 = *(const float4*)(W + 1536 + k0);
    float4 wb1 = *(const float4*)(W + 1536 + k0 + 4);

    float xs[8] = {x0.x, x0.y, x0.z, x0.w, x1.x, x1.y, x1.z, x1.w};
    float w0[8] = {wa0.x, wa0.y, wa0.z, wa0.w, wa1.x, wa1.y, wa1.z, wa1.w};
    float w1[8] = {wb0.x, wb0.y, wb0.z, wb0.w, wb1.x, wb1.y, wb1.z, wb1.w};

    PackH8 a0, a1, bh, bl;
#pragma unroll
    for (int t = 0; t < 8; t++) {
        a0.h[t] = __float2half_rn(xs[t] * w0[t]);
        a1.h[t] = __float2half_rn(xs[t] * w1[t]);
        __half h = __float2half_rn(xs[t]);
        bh.h[t] = h;
        bl.h[t] = __float2half_rn(xs[t] - __half2float(h));
    }
    size_t off = (size_t)i * HDIM + k0;
    *(uint4*)(&g_img[0][off]) = a0.v;
    *(uint4*)(&g_img[1][off]) = a1.v;
    *(uint4*)(&g_img[2][off]) = bh.v;
    *(uint4*)(&g_img[3][off]) = bl.v;
}

// ---------------------------------------------------------------------------
__device__ __forceinline__ uint32_t smem_u32(const void* p) {
    uint32_t a;
    asm("{ .reg .u64 t; cvta.to.shared.u64 t, %1; cvt.u32.u64 %0, t; }"
        : "=r"(a) : "l"(p));
    return a;
}

__device__ __forceinline__ void cp16(uint32_t dst, const void* src) {
    asm volatile("cp.async.cg.shared.global [%0], [%1], 16;"
                 :: "r"(dst), "l"(src) : "memory");
}

__device__ __forceinline__ void ldsm4(uint32_t* r, uint32_t addr) {
    asm volatile("ldmatrix.sync.aligned.m8n8.x4.shared.b16 {%0,%1,%2,%3}, [%4];"
                 : "=r"(r[0]), "=r"(r[1]), "=r"(r[2]), "=r"(r[3]) : "r"(addr));
}

__device__ __forceinline__ void mmaf16(float* c, const uint32_t* a,
                                       uint32_t b0, uint32_t b1) {
    asm volatile(
        "mma.sync.aligned.m16n8k16.row.col.f32.f16.f16.f32 "
        "{%0,%1,%2,%3}, {%4,%5,%6,%7}, {%8,%9}, {%0,%1,%2,%3};"
        : "+f"(c[0]), "+f"(c[1]), "+f"(c[2]), "+f"(c[3])
        : "r"(a[0]), "r"(a[1]), "r"(a[2]), "r"(a[3]), "r"(b0), "r"(b1));
}

__device__ __forceinline__ void grp_bar(int id) {
    asm volatile("bar.sync %0, 128;" :: "r"(id) : "memory");
}

__global__ void __launch_bounds__(512, 1)
pairwise_mma_kernel(const float* __restrict__ bias, float* __restrict__ out)
{
    // Triangular decode: blockIdx.x in [0,136) -> (bi, bj), bj >= bi
    int t = blockIdx.x;
    int bi = 0;
    while (t >= 16 - bi) { t -= 16 - bi; bi++; }
    const int bj = bi + t;

    extern __shared__ __align__(16) char smem[];
    const uint32_t sbase = smem_u32(smem);

    const int tid  = threadIdx.x;
    const int grp  = tid >> 7;        // K-group 0..3
    const int gtid = tid & 127;
    const int wid  = gtid >> 5;
    const int lane = tid & 31;
    const int wm = wid >> 1;          // warp row (0..1) of 16
    const int wn = wid & 1;           // warp col (0..1) of 16

    const __half* src[NTILE];
    src[0] = &g_img[0][(size_t)(bi * 32) * HDIM];
    src[1] = &g_img[1][(size_t)(bi * 32) * HDIM];
    src[2] = &g_img[2][(size_t)(bj * 32) * HDIM];
    src[3] = &g_img[3][(size_t)(bj * 32) * HDIM];

    const uint32_t gb = sbase + grp * GRP_B;
    const int lrow = gtid >> 2;       // 0..31 tile row
    const int lc   = gtid & 3;        // 16B chunk within 64B row
    const int kofs = grp * NKCG;      // this group's first chunk

    auto issue = [&](int kc, int sl) {
        const uint32_t dbase = gb + sl * STAGE_B + lrow * ROW_B + lc * 16;
        const int kcol = (kofs + kc) * KC + lc * 8;
#pragma unroll
        for (int q = 0; q < NTILE; q++)
            cp16(dbase + q * TILE_B, src[q] + (size_t)lrow * HDIM + kcol);
    };

    // acc[ch][term][nf][4], term: 0 = A*Bhi, 1 = A*Blo
    float acc0[2][2][4] = {};
    float acc1[2][2][4] = {};

    const uint32_t arow = (uint32_t)(wm * 16 + (lane & 15)) * ROW_B
                        + ((lane >> 4) << 4);
    const uint32_t brow = (uint32_t)(wn * 16 + (lane & 15)) * ROW_B
                        + ((lane >> 4) << 4);

    auto compute = [&](int sl) {
        const uint32_t tb = gb + sl * STAGE_B;
#pragma unroll
        for (int h = 0; h < 2; h++) {           // two k16 slices of k32
            uint32_t a0[4], a1[4], bh[4], bl[4];
            ldsm4(a0, tb + 0 * TILE_B + arow + h * 32);
            ldsm4(a1, tb + 1 * TILE_B + arow + h * 32);
            ldsm4(bh, tb + 2 * TILE_B + brow + h * 32);
            ldsm4(bl, tb + 3 * TILE_B + brow + h * 32);
#pragma unroll
            for (int nf = 0; nf < 2; nf++) {
                mmaf16(acc0[0][nf], a0, bh[nf], bh[nf + 2]);
                mmaf16(acc1[0][nf], a1, bh[nf], bh[nf + 2]);
                mmaf16(acc0[1][nf], a0, bl[nf], bl[nf + 2]);
                mmaf16(acc1[1][nf], a1, bl[nf], bl[nf + 2]);
            }
        }
    };

    // ---- 4-stage cp.async pipeline, ONE barrier per chunk ----
    // issue(kc+2) overwrites stage (kc+2)%4, last read by compute(kc-2);
    // the barrier at iter kc-1 separates them -> no data race.
    const int barid = grp + 1;
    issue(0, 0);
    asm volatile("cp.async.commit_group;" ::: "memory");
    issue(1, 1);
    asm volatile("cp.async.commit_group;" ::: "memory");

#pragma unroll 1
    for (int kc = 0; kc < NKCG; kc++) {
        if (kc + 2 < NKCG) {
            issue(kc + 2, (kc + 2) & (NSTAGE - 1));
            asm volatile("cp.async.commit_group;" ::: "memory");
        }
        const int rem = NKCG - 1 - kc;   // chunks issued beyond kc
        if (rem >= 2)
            asm volatile("cp.async.wait_group 2;" ::: "memory");
        else if (rem == 1)
            asm volatile("cp.async.wait_group 1;" ::: "memory");
        else
            asm volatile("cp.async.wait_group 0;" ::: "memory");
        grp_bar(barid);
        compute(kc & (NSTAGE - 1));
    }

    // ---- combine 4 K-quarters via smem, then coalesced STG ----
    __syncthreads();
    float* fin  = (float*)smem;
    float* part = (float*)(smem + FIN_B);

    if (grp != 0) {
        float* pb = part + (grp - 1) * PART_FLOATS;
#pragma unroll
        for (int nf = 0; nf < 2; nf++)
#pragma unroll
            for (int r = 0; r < 4; r++) {
                const int idx = ((gtid * 2 + nf) * 4 + r) * 2;
                pb[idx + 0] = acc0[0][nf][r] + acc0[1][nf][r];
                pb[idx + 1] = acc1[0][nf][r] + acc1[1][nf][r];
            }
    }
    __syncthreads();

    if (grp == 0) {
        const float bv0 = bias[0];
        const float bv1 = bias[1];
#pragma unroll
        for (int nf = 0; nf < 2; nf++)
#pragma unroll
            for (int r = 0; r < 4; r++) {
                const int idx = ((gtid * 2 + nf) * 4 + r) * 2;
                const float v0 = acc0[0][nf][r] + acc0[1][nf][r]
                               + part[idx] + part[PART_FLOATS + idx]
                               + part[2 * PART_FLOATS + idx] + bv0;
                const float v1 = acc1[0][nf][r] + acc1[1][nf][r]
                               + part[idx + 1] + part[PART_FLOATS + idx + 1]
                               + part[2 * PART_FLOATS + idx + 1] + bv1;
                const int ii = wm * 16 + (lane >> 2) + ((r >> 1) << 3);
                const int jj = wn * 16 + nf * 8 + ((lane & 3) << 1) + (r & 1);
                fin[ii * FIN_STRIDE + jj * 2 + 0] = v0;
                fin[ii * FIN_STRIDE + jj * 2 + 1] = v1;
            }
    }
    __syncthreads();

    const int ib = bi * 32;
    const int jb = bj * 32;

    // Direct pass: 512 threads, each 2 cols of one row (contiguous float2)
    {
        const int ii = tid >> 4;
        const int j0 = (tid & 15) * 2;
        const int gi = ib + ii;
        if (gi >= 1 && gi <= 510) {
            float* orow = out + (size_t)(gi - 1) * 1020;
#pragma unroll
            for (int u = 0; u < 2; u++) {
                const int jj = j0 + u;
                const int gj = jb + jj;
                if (gj >= 1 && gj <= 510) {
                    float2 v = *(float2*)(fin + ii * FIN_STRIDE + jj * 2);
                    *(float2*)(orow + (size_t)(gj - 1) * 2) = v;
                }
            }
        }
    }
    // Mirror pass (off-diagonal tiles)
    if (bi != bj) {
        const int jj = tid >> 4;
        const int i0 = (tid & 15) * 2;
        const int gj = jb + jj;
        if (gj >= 1 && gj <= 510) {
            float* orow = out + (size_t)(gj - 1) * 1020;
#pragma unroll
            for (int u = 0; u < 2; u++) {
                const int ii = i0 + u;
                const int gi = ib + ii;
                if (gi >= 1 && gi <= 510) {
                    float2 v = *(float2*)(fin + ii * FIN_STRIDE + jj * 2);
                    *(float2*)(orow + (size_t)(gi - 1) * 2) = v;
                }
            }
        }
    }
}

// ---------------------------------------------------------------------------
extern "C" void kernel_launch(void* const* d_in, const int* in_sizes, int n_in,
                              void* d_out, int out_size)
{
    const float* x = (const float*)d_in[0];   // (1, 512, 768)
    const float* W = (const float*)d_in[1];   // (2, 1536)
    const float* b = (const float*)d_in[2];   // (2,)
    float* out = (float*)d_out;               // (510, 510, 2)

    cudaFuncSetAttribute(pairwise_mma_kernel,
                         cudaFuncAttributeMaxDynamicSharedMemorySize, SMEM_TOTAL);

    prep_kernel<<<192, 256>>>(x, W);
    pairwise_mma_kernel<<<136, 512, SMEM_TOTAL>>>(b, out);
}

// round 12
// speedup vs baseline: 1.4963x; 1.1222x over previous
#include <cuda_runtime.h>
#include <cuda_fp16.h>
#include <cstdint>

// out[i,j,o] = sum_h x[i+1,h]*x[j+1,h]*W[o,h] + b[o]
// (diff/W2 term is antisymmetric -> cancels under (P+P^T)/2 symmetrization)
//
// D_o = A_o B^T, A_o = X .* w_o, B = X (512x768 f32)
// fp32 approximated by ASYMMETRIC fp16 split: a*b ~= fp16(a)*(bhi+blo)
// (2 MMAs per k16 per channel; measured rel_err ~2e-4 < 1e-3).
// Prep pre-converts 4 fp16 images. Main kernel holds the FULL K=768 working
// set (192 KB) resident in smem: bulk cp.async in 2 mega-chunks, then a
// barrier-free LDSM+HMMA loop (2 syncs total). 16 warps = 4 K-groups x 4.
// Upper-tri 32x32 tiles + mirror, smem combine, coalesced STG. No atomics.

#define HDIM 768
#define KM 384                     // K per mega-chunk (2 chunks)
#define ROW_B 784                  // 768 B data + 16 B pad (conflict-free LDSM)
#define TILE_B (32 * ROW_B)        // 25088 B per image per chunk
#define NTILE 4                    // A0h A1h Bh Bl
#define STAGE_B (NTILE * TILE_B)   // 100352 B
#define SMEM_TOTAL (2 * STAGE_B)   // 200704 B (1 CTA/SM)
#define KG 96                      // K per group within a mega-chunk (384/4)
#define FIN_STRIDE 66
#define FIN_B 8448                 // 32*66*4
#define PART_FLOATS 2048           // 32*32*2

// fp16 images: 0:A0h 1:A1h 2:Bh 3:Bl  (row-major [512][768])
__device__ __half g_img[4][512 * HDIM];

// ---------------------------------------------------------------------------
union PackH8 { __half h[8]; uint4 v; };

__global__ void prep_kernel(const float* __restrict__ x,
                            const float* __restrict__ W)
{
    int gid = blockIdx.x * blockDim.x + threadIdx.x;
    if (gid >= 512 * (HDIM / 8)) return;
    int i  = gid / (HDIM / 8);
    int k0 = (gid % (HDIM / 8)) * 8;

    float4 x0 = *(const float4*)(x + (size_t)i * HDIM + k0);
    float4 x1 = *(const float4*)(x + (size_t)i * HDIM + k0 + 4);
    float4 wa0 = *(const float4*)(W + k0);
    float4 wa1 = *(const float4*)(W + k0 + 4);
    float4 wb0 = *(const float4*)(W + 1536 + k0);
    float4 wb1 = *(const float4*)(W + 1536 + k0 + 4);

    float xs[8] = {x0.x, x0.y, x0.z, x0.w, x1.x, x1.y, x1.z, x1.w};
    float w0[8] = {wa0.x, wa0.y, wa0.z, wa0.w, wa1.x, wa1.y, wa1.z, wa1.w};
    float w1[8] = {wb0.x, wb0.y, wb0.z, wb0.w, wb1.x, wb1.y, wb1.z, wb1.w};

    PackH8 a0, a1, bh, bl;
#pragma unroll
    for (int t = 0; t < 8; t++) {
        a0.h[t] = __float2half_rn(xs[t] * w0[t]);
        a1.h[t] = __float2half_rn(xs[t] * w1[t]);
        __half h = __float2half_rn(xs[t]);
        bh.h[t] = h;
        bl.h[t] = __float2half_rn(xs[t] - __half2float(h));
    }
    size_t off = (size_t)i * HDIM + k0;
    *(uint4*)(&g_img[0][off]) = a0.v;
    *(uint4*)(&g_img[1][off]) = a1.v;
    *(uint4*)(&g_img[2][off]) = bh.v;
    *(uint4*)(&g_img[3][off]) = bl.v;
}

// ---------------------------------------------------------------------------
__device__ __forceinline__ uint32_t smem_u32(const void* p) {
    uint32_t a;
    asm("{ .reg .u64 t; cvta.to.shared.u64 t, %1; cvt.u32.u64 %0, t; }"
        : "=r"(a) : "l"(p));
    return a;
}

__device__ __forceinline__ void cp16(uint32_t dst, const void* src) {
    asm volatile("cp.async.cg.shared.global [%0], [%1], 16;"
                 :: "r"(dst), "l"(src) : "memory");
}

__device__ __forceinline__ void ldsm4(uint32_t* r, uint32_t addr) {
    asm volatile("ldmatrix.sync.aligned.m8n8.x4.shared.b16 {%0,%1,%2,%3}, [%4];"
                 : "=r"(r[0]), "=r"(r[1]), "=r"(r[2]), "=r"(r[3]) : "r"(addr));
}

__device__ __forceinline__ void mmaf16(float* c, const uint32_t* a,
                                       uint32_t b0, uint32_t b1) {
    asm volatile(
        "mma.sync.aligned.m16n8k16.row.col.f32.f16.f16.f32 "
        "{%0,%1,%2,%3}, {%4,%5,%6,%7}, {%8,%9}, {%0,%1,%2,%3};"
        : "+f"(c[0]), "+f"(c[1]), "+f"(c[2]), "+f"(c[3])
        : "r"(a[0]), "r"(a[1]), "r"(a[2]), "r"(a[3]), "r"(b0), "r"(b1));
}

__global__ void __launch_bounds__(512, 1)
pairwise_mma_kernel(const float* __restrict__ bias, float* __restrict__ out)
{
    // Triangular decode: blockIdx.x in [0,136) -> (bi, bj), bj >= bi
    int t = blockIdx.x;
    int bi = 0;
    while (t >= 16 - bi) { t -= 16 - bi; bi++; }
    const int bj = bi + t;

    extern __shared__ __align__(16) char smem[];
    const uint32_t sbase = smem_u32(smem);

    const int tid  = threadIdx.x;
    const int grp  = tid >> 7;        // K-group 0..3
    const int gtid = tid & 127;
    const int wid  = gtid >> 5;
    const int lane = tid & 31;
    const int wm = wid >> 1;          // warp row (0..1) of 16
    const int wn = wid & 1;           // warp col (0..1) of 16

    const __half* src[NTILE];
    src[0] = &g_img[0][(size_t)(bi * 32) * HDIM];
    src[1] = &g_img[1][(size_t)(bi * 32) * HDIM];
    src[2] = &g_img[2][(size_t)(bj * 32) * HDIM];
    src[3] = &g_img[3][(size_t)(bj * 32) * HDIM];

    // ---- bulk load: whole-CTA cooperative, 2 mega-chunks of K=384 ----
    // Per image per chunk: 32 rows x 48 x 16B = 1536 cp; 512 thr -> 3 each.
    auto issue = [&](int st) {
        const uint32_t stb = sbase + st * STAGE_B;
#pragma unroll
        for (int q = 0; q < NTILE; q++) {
#pragma unroll
            for (int p = 0; p < 3; p++) {
                const int id  = tid + p * 512;      // 0..1535
                const int row = id / 48;
                const int c   = id % 48;
                cp16(stb + q * TILE_B + row * ROW_B + c * 16,
                     src[q] + (size_t)row * HDIM + st * KM + c * 8);
            }
        }
    };

    issue(0);
    asm volatile("cp.async.commit_group;" ::: "memory");
    issue(1);
    asm volatile("cp.async.commit_group;" ::: "memory");

    // acc[ch][term][nf][4], term: 0 = A*Bhi, 1 = A*Blo
    float acc0[2][2][4] = {};
    float acc1[2][2][4] = {};

    const uint32_t arow = (uint32_t)(wm * 16 + (lane & 15)) * ROW_B
                        + ((lane >> 4) << 4);
    const uint32_t brow = (uint32_t)(wn * 16 + (lane & 15)) * ROW_B
                        + ((lane >> 4) << 4);

    // Barrier-free compute over resident data: group g covers K-cols
    // [g*96, g*96+96) of this mega-chunk = 6 k16 slices.
    auto compute = [&](int st) {
        const uint32_t tb = sbase + st * STAGE_B;
        const uint32_t kb = (uint32_t)(grp * KG * 2);   // byte col base
#pragma unroll
        for (int h = 0; h < 6; h++) {
            const uint32_t co = kb + h * 32;
            uint32_t a0[4], a1[4], bh[4], bl[4];
            ldsm4(a0, tb + 0 * TILE_B + arow + co);
            ldsm4(a1, tb + 1 * TILE_B + arow + co);
            ldsm4(bh, tb + 2 * TILE_B + brow + co);
            ldsm4(bl, tb + 3 * TILE_B + brow + co);
#pragma unroll
            for (int nf = 0; nf < 2; nf++) {
                mmaf16(acc0[0][nf], a0, bh[nf], bh[nf + 2]);
                mmaf16(acc1[0][nf], a1, bh[nf], bh[nf + 2]);
                mmaf16(acc0[1][nf], a0, bl[nf], bl[nf + 2]);
                mmaf16(acc1[1][nf], a1, bl[nf], bl[nf + 2]);
            }
        }
    };

    asm volatile("cp.async.wait_group 1;" ::: "memory");
    __syncthreads();
    compute(0);                       // overlaps the stage-1 load
    asm volatile("cp.async.wait_group 0;" ::: "memory");
    __syncthreads();
    compute(1);

    // ---- combine 4 K-quarters via smem, then coalesced STG ----
    __syncthreads();
    float* fin  = (float*)smem;
    float* part = (float*)(smem + FIN_B);

    if (grp != 0) {
        float* pb = part + (grp - 1) * PART_FLOATS;
#pragma unroll
        for (int nf = 0; nf < 2; nf++)
#pragma unroll
            for (int r = 0; r < 4; r++) {
                const int idx = ((gtid * 2 + nf) * 4 + r) * 2;
                pb[idx + 0] = acc0[0][nf][r] + acc0[1][nf][r];
                pb[idx + 1] = acc1[0][nf][r] + acc1[1][nf][r];
            }
    }
    __syncthreads();

    if (grp == 0) {
        const float bv0 = bias[0];
        const float bv1 = bias[1];
#pragma unroll
        for (int nf = 0; nf < 2; nf++)
#pragma unroll
            for (int r = 0; r < 4; r++) {
                const int idx = ((gtid * 2 + nf) * 4 + r) * 2;
                const float v0 = acc0[0][nf][r] + acc0[1][nf][r]
                               + part[idx] + part[PART_FLOATS + idx]
                               + part[2 * PART_FLOATS + idx] + bv0;
                const float v1 = acc1[0][nf][r] + acc1[1][nf][r]
                               + part[idx + 1] + part[PART_FLOATS + idx + 1]
                               + part[2 * PART_FLOATS + idx + 1] + bv1;
                const int ii = wm * 16 + (lane >> 2) + ((r >> 1) << 3);
                const int jj = wn * 16 + nf * 8 + ((lane & 3) << 1) + (r & 1);
                fin[ii * FIN_STRIDE + jj * 2 + 0] = v0;
                fin[ii * FIN_STRIDE + jj * 2 + 1] = v1;
            }
    }
    __syncthreads();

    const int ib = bi * 32;
    const int jb = bj * 32;

    // Direct pass: 512 threads, each one float2 x2 of a contiguous row
    {
        const int ii = tid >> 4;
        const int j0 = (tid & 15) * 2;
        const int gi = ib + ii;
        if (gi >= 1 && gi <= 510) {
            float* orow = out + (size_t)(gi - 1) * 1020;
#pragma unroll
            for (int u = 0; u < 2; u++) {
                const int jj = j0 + u;
                const int gj = jb + jj;
                if (gj >= 1 && gj <= 510) {
                    float2 v = *(float2*)(fin + ii * FIN_STRIDE + jj * 2);
                    *(float2*)(orow + (size_t)(gj - 1) * 2) = v;
                }
            }
        }
    }
    // Mirror pass (off-diagonal tiles)
    if (bi != bj) {
        const int jj = tid >> 4;
        const int i0 = (tid & 15) * 2;
        const int gj = jb + jj;
        if (gj >= 1 && gj <= 510) {
            float* orow = out + (size_t)(gj - 1) * 1020;
#pragma unroll
            for (int u = 0; u < 2; u++) {
                const int ii = i0 + u;
                const int gi = ib + ii;
                if (gi >= 1 && gi <= 510) {
                    float2 v = *(float2*)(fin + ii * FIN_STRIDE + jj * 2);
                    *(float2*)(orow + (size_t)(gi - 1) * 2) = v;
                }
            }
        }
    }
}

// ---------------------------------------------------------------------------
extern "C" void kernel_launch(void* const* d_in, const int* in_sizes, int n_in,
                              void* d_out, int out_size)
{
    const float* x = (const float*)d_in[0];   // (1, 512, 768)
    const float* W = (const float*)d_in[1];   // (2, 1536)
    const float* b = (const float*)d_in[2];   // (2,)
    float* out = (float*)d_out;               // (510, 510, 2)

    cudaFuncSetAttribute(pairwise_mma_kernel,
                         cudaFuncAttributeMaxDynamicSharedMemorySize, SMEM_TOTAL);

    prep_kernel<<<192, 256>>>(x, W);
    pairwise_mma_kernel<<<136, 512, SMEM_TOTAL>>>(b, out);
}